// round 3
// baseline (speedup 1.0000x reference)
#include <cuda_runtime.h>

// Fixed problem shape
#define NMOL   256
#define NATOM  512
#define KNB    32
#define NTOT   (NMOL * NATOM)            // 131072 atoms
#define EDG    ((size_t)NTOT * KNB)      // 4194304 edges
#define TPB    128                       // 32 atoms per block, 4 threads/atom
#define APB    (TPB / 4)
#define CAPT   48                        // per-thread candidate cap (3 groups of 16)
#define NGT    3
#define INFK   0xFFFFFFFFu
#define INF64  0xFFFFFFFFFFFFFFFFull

// smem: float4 sp[512] (8KB) + u32 keys sd2[CAPT*TPB] (24KB) = 32KB -> 7 blocks/SM
#define SMEM_BYTES (NATOM * 16 + CAPT * TPB * 4)

__device__ __forceinline__ unsigned long long umin64(unsigned long long a,
                                                     unsigned long long b)
{ return a < b ? a : b; }

// argmin over one 16-slot group; 'excl' slot (absolute) treated as INF (-1 = none).
// Tie -> lowest slot (== lowest j in insertion order).
__device__ __forceinline__ void scan_group(const unsigned int* mybuf, int g, int excl,
                                           unsigned int& bv, int& bs)
{
    unsigned int kv[16];
    const int base = g << 4;
    #pragma unroll
    for (int u = 0; u < 16; ++u) {
        unsigned int v = mybuf[(base + u) * TPB];
        kv[u] = (base + u == excl) ? INFK : v;
    }
    unsigned int m = kv[0];
    #pragma unroll
    for (int u = 1; u < 16; ++u) m = umin(m, kv[u]);
    unsigned int msk = 0;
    #pragma unroll
    for (int u = 0; u < 16; ++u) msk |= (kv[u] == m) ? (1u << u) : 0u;
    bv = m;
    bs = base + (__ffs(msk) - 1);
}

__global__ void __launch_bounds__(TPB)
topo_kernel(const float* __restrict__ x, float* __restrict__ out)
{
    extern __shared__ char smem[];
    float4*       sp  = (float4*)smem;
    unsigned int* sd2 = (unsigned int*)(smem + NATOM * 16);

    const int tid     = threadIdx.x;
    const int sub     = tid & 3;                      // sub-thread within atom
    const int gatom   = blockIdx.x * APB + (tid >> 2);
    const int molbase = gatom & ~(NATOM - 1);
    const int i       = gatom & (NATOM - 1);

    for (int t = tid; t < NATOM; t += TPB) {
        const int a = molbase + t;
        sp[t] = make_float4(x[3 * a + 0], x[3 * a + 1], x[3 * a + 2], 0.0f);
    }
    __syncthreads();

    const float px = sp[i].x, py = sp[i].y, pz = sp[i].z;

    // ---- Phase 1: collect candidates for j = sub (mod 4), exact f32 arithmetic ----
    unsigned short jloc[CAPT];
    unsigned int*  mybuf = sd2 + tid;                 // sd2[slot*TPB + tid]: conflict-free
    int cnt = 0;

    #pragma unroll 4
    for (int j = sub; j < NATOM; j += 4) {
        const float4 q  = sp[j];
        const float  dx = q.x - px;
        const float  dy = q.y - py;
        const float  dz = q.z - pz;
        const float  d2 = __fadd_rn(__fadd_rn(__fmul_rn(dx, dx), __fmul_rn(dy, dy)),
                                    __fmul_rn(dz, dz));
        if (d2 < 1.0f && d2 > 0.0f) {
            const unsigned int kb = __float_as_uint(d2);
            if (cnt < CAPT) {
                mybuf[cnt * TPB] = kb;
                jloc[cnt]        = (unsigned short)j;
                ++cnt;
            } else {
                // exact overflow handling: evict largest (d2, j). Top-32 of the atom
                // contains <=32 from this residue class, so smallest-48 always suffices.
                unsigned long long wk = 0; int ws = 0;
                for (int t = 0; t < CAPT; ++t) {
                    unsigned long long kk =
                        ((unsigned long long)mybuf[t * TPB] << 32) | jloc[t];
                    if (kk > wk) { wk = kk; ws = t; }
                }
                const unsigned long long nk = ((unsigned long long)kb << 32) | (unsigned)j;
                if (nk < wk) { mybuf[ws * TPB] = kb; jloc[ws] = (unsigned short)j; }
            }
        }
    }

    // pad the partial group so group scans see INF
    const int pad = (cnt + 15) & ~15;
    for (int t = cnt; t < pad; ++t) mybuf[t * TPB] = INFK;

    // ---- Phase 1b: per-group minima in registers ----
    unsigned int gv0, gv1, gv2; int gs0, gs1, gs2;
    if (0 < pad) scan_group(mybuf, 0, -1, gv0, gs0); else { gv0 = INFK; gs0 = 0;  }
    if (16 < pad) scan_group(mybuf, 1, -1, gv1, gs1); else { gv1 = INFK; gs1 = 16; }
    if (32 < pad) scan_group(mybuf, 2, -1, gv2, gs2); else { gv2 = INFK; gs2 = 32; }

    // thread-best key (d2bits, global j); INF sentinel when exhausted
    unsigned int tv = gv0; int ts = gs0;
    if (gv1 < tv) { tv = gv1; ts = gs1; }
    if (gv2 < tv) { tv = gv2; ts = gs2; }
    unsigned long long tkey = (tv == INFK) ? INF64
                            : (((unsigned long long)tv << 32) | (unsigned)jloc[ts]);

    // ---- Phase 2: 32 rounds; winner selected across 4 threads via shfl butterfly ----
    unsigned long long skey[8];                       // this thread's 8 output slots

    #pragma unroll
    for (int r = 0; r < KNB; ++r) {
        unsigned long long k = tkey;
        k = umin64(k, __shfl_xor_sync(0xffffffffu, k, 1));
        k = umin64(k, __shfl_xor_sync(0xffffffffu, k, 2));

        if (sub == (r >> 3)) skey[r & 7] = k;         // record (static idx when unrolled)

        if (tkey == k && k != INF64) {                // unique winner (j unique)
            const int bg = ts >> 4;
            mybuf[ts * TPB] = INFK;                   // for future rescans of this group
            unsigned int nv; int ns;
            scan_group(mybuf, bg, ts, nv, ns);        // extracted slot masked in-register
            if (bg == 0) { gv0 = nv; gs0 = ns; }
            if (bg == 1) { gv1 = nv; gs1 = ns; }
            if (bg == 2) { gv2 = nv; gs2 = ns; }
            tv = gv0; ts = gs0;
            if (gv1 < tv) { tv = gv1; ts = gs1; }
            if (gv2 < tv) { tv = gv2; ts = gs2; }
            tkey = (tv == INFK) ? INF64
                 : (((unsigned long long)tv << 32) | (unsigned)jloc[ts]);
        }
    }

    // ---- Phase 3: emit 8 slots per thread, all float4, fully coalesced ----
    const int so = sub * 8;                           // this thread's slot base
    float* obi  = out + (size_t)gatom * KNB + so;
    float* obj  = out + EDG + (size_t)gatom * KNB + so;
    float* ovec = out + 2 * EDG + (size_t)gatom * (3 * KNB) + 3 * so;
    float* odst = out + 5 * EDG + (size_t)gatom * KNB + so;
    float* oval = out + 6 * EDG + (size_t)gatom * KNB + so;

    const float fgi = (float)gatom;

    #pragma unroll
    for (int qb = 0; qb < 2; ++qb) {
        float bi4[4], bj4[4], dd4[4], vv4[4], vec12[12];
        #pragma unroll
        for (int u = 0; u < 4; ++u) {
            const unsigned long long sk = skey[qb * 4 + u];
            const unsigned int db = (unsigned int)(sk >> 32);
            const bool ok = (db != INFK);
            const int  j  = (int)(sk & 0xFFFFFFFFu) & (NATOM - 1);
            const float4 qq = sp[j];
            vec12[u * 3 + 0] = ok ? (qq.x - px) : 0.0f;
            vec12[u * 3 + 1] = ok ? (qq.y - py) : 0.0f;
            vec12[u * 3 + 2] = ok ? (qq.z - pz) : 0.0f;
            bi4[u] = ok ? fgi : -1.0f;
            bj4[u] = ok ? (float)(molbase + j) : -1.0f;
            dd4[u] = ok ? sqrtf(__uint_as_float(db)) : 0.0f;
            vv4[u] = ok ? 1.0f : 0.0f;
        }
        *(float4*)(obi  + qb * 4)      = make_float4(bi4[0], bi4[1], bi4[2], bi4[3]);
        *(float4*)(obj  + qb * 4)      = make_float4(bj4[0], bj4[1], bj4[2], bj4[3]);
        *(float4*)(odst + qb * 4)      = make_float4(dd4[0], dd4[1], dd4[2], dd4[3]);
        *(float4*)(oval + qb * 4)      = make_float4(vv4[0], vv4[1], vv4[2], vv4[3]);
        *(float4*)(ovec + qb * 12 + 0) = make_float4(vec12[0], vec12[1], vec12[2],  vec12[3]);
        *(float4*)(ovec + qb * 12 + 4) = make_float4(vec12[4], vec12[5], vec12[6],  vec12[7]);
        *(float4*)(ovec + qb * 12 + 8) = make_float4(vec12[8], vec12[9], vec12[10], vec12[11]);
    }
}

extern "C" void kernel_launch(void* const* d_in, const int* in_sizes, int n_in,
                              void* d_out, int out_size)
{
    const float* x   = (const float*)d_in[0];
    float*       out = (float*)d_out;

    cudaFuncSetAttribute(topo_kernel, cudaFuncAttributeMaxDynamicSharedMemorySize,
                         SMEM_BYTES);
    topo_kernel<<<NTOT / APB, TPB, SMEM_BYTES>>>(x, out);
}